// round 5
// baseline (speedup 1.0000x reference)
#include <cuda_runtime.h>
#include <math.h>

// Fixed shapes (from reference setup_inputs)
#define D_IN    4096
#define D_OUT   4096
#define NROWS   8192          // B*S
#define RANK    8
#define SCALING 2.0f          // ALPHA/RANK
#define EPS     1e-8f
#define NC4     (D_IN / 4)    // 1024 float4 columns per row
#define NPAIR   36            // upper-triangle count for 8x8 Gram

// Scratch (allocation-free: __device__ globals)
__device__ float g_w2[D_OUT];            // ||bw_row||^2
__device__ float g_wA[D_OUT * RANK];     // bw @ A^T
__device__ float g_lxr[NROWS * RANK];    // x @ A^T
__device__ float g_G[RANK * RANK];       // A @ A^T
__device__ float g_mag_scale[D_OUT];
__device__ float g_Bs[D_OUT * RANK];     // B[o,r] * SCALING * mag_scale[o]

__device__ __forceinline__ float dot4(float4 a, float4 b) {
    return a.x * b.x + a.y * b.y + a.z * b.z + a.w * b.w;
}

// ---------------------------------------------------------------------------
// Gram kernel: G = A @ A^T  (8x8). One block.
// ---------------------------------------------------------------------------
__global__ __launch_bounds__(256)
void gram_kernel(const float* __restrict__ A)
{
    const int tid = threadIdx.x;
    const float4* __restrict__ A4 = (const float4*)A;

    float acc[NPAIR];
#pragma unroll
    for (int k = 0; k < NPAIR; k++) acc[k] = 0.f;

    for (int c = tid; c < NC4; c += 256) {
        float4 a[RANK];
#pragma unroll
        for (int r = 0; r < RANK; r++) a[r] = __ldg(&A4[r * NC4 + c]);
        int k = 0;
#pragma unroll
        for (int r = 0; r < RANK; r++)
#pragma unroll
            for (int r2 = r; r2 < RANK; r2++)
                acc[k++] += dot4(a[r], a[r2]);
    }

#pragma unroll
    for (int k = 0; k < NPAIR; k++)
#pragma unroll
        for (int off = 16; off; off >>= 1)
            acc[k] += __shfl_xor_sync(0xffffffffu, acc[k], off);

    __shared__ float red[8][NPAIR];
    const int warp = tid >> 5, lane = tid & 31;
    if (lane == 0)
#pragma unroll
        for (int k = 0; k < NPAIR; k++) red[warp][k] = acc[k];
    __syncthreads();

    if (tid < NPAIR) {
        float s = 0.f;
#pragma unroll
        for (int w = 0; w < 8; w++) s += red[w][tid];
        // map linear upper-triangle index -> (r, r2)
        int k = tid, r = 0;
        while (k >= RANK - r) { k -= RANK - r; r++; }
        int r2 = r + k;
        g_G[r * RANK + r2] = s;
        g_G[r2 * RANK + r] = s;
    }
}

// ---------------------------------------------------------------------------
// rowdot: for rows 0..4095   (bw):  wA[o,r] = bw_o . A_r,  w2[o] = ||bw_o||^2
//         for rows 4096..12287 (x): lxr[s,r] = x_s . A_r
// 4 rows per block. Streamed rows use .cs (evict-first); A uses __ldg and
// stays L1-resident across the ~20 sequential blocks per SM (128KB < L1).
// ---------------------------------------------------------------------------
__global__ __launch_bounds__(256, 3)
void rowdot_kernel(const float* __restrict__ bw,
                   const float* __restrict__ x)
{
    const int tid   = threadIdx.x;
    const int grow0 = blockIdx.x * 4;            // 0..12287
    const bool is_bw = (grow0 < D_OUT);
    const float* __restrict__ src =
        is_bw ? bw + (size_t)grow0 * D_IN
              : x  + (size_t)(grow0 - D_OUT) * D_IN;
    // A lives right after bw? No — passed separately via global symbol trick:
    // we bind A through a __device__ pointer set below.
    extern __device__ const float* g_Aptr;       // fwd decl (defined after)

    const float4* __restrict__ A4 = (const float4*)g_Aptr;

    float acc[4][RANK];
    float sq[4] = {0.f, 0.f, 0.f, 0.f};
#pragma unroll
    for (int n = 0; n < 4; n++)
#pragma unroll
        for (int r = 0; r < RANK; r++) acc[n][r] = 0.f;

    for (int c = tid; c < NC4; c += 256) {
        float4 v[4];
#pragma unroll
        for (int n = 0; n < 4; n++)
            v[n] = __ldcs(((const float4*)(src + (size_t)n * D_IN)) + c);

#pragma unroll
        for (int r = 0; r < RANK; r++) {
            float4 a = __ldg(&A4[r * NC4 + c]);
#pragma unroll
            for (int n = 0; n < 4; n++)
                acc[n][r] += dot4(v[n], a);
        }
        if (is_bw) {
#pragma unroll
            for (int n = 0; n < 4; n++)
                sq[n] += dot4(v[n], v[n]);
        }
    }

    // reduce 4*(8+1) = 36 values: warp shuffle, then cross-warp via shared
#pragma unroll
    for (int n = 0; n < 4; n++) {
#pragma unroll
        for (int r = 0; r < RANK; r++)
#pragma unroll
            for (int off = 16; off; off >>= 1)
                acc[n][r] += __shfl_xor_sync(0xffffffffu, acc[n][r], off);
#pragma unroll
        for (int off = 16; off; off >>= 1)
            sq[n] += __shfl_xor_sync(0xffffffffu, sq[n], off);
    }

    __shared__ float red[8][36];
    const int warp = tid >> 5, lane = tid & 31;
    if (lane == 0) {
#pragma unroll
        for (int n = 0; n < 4; n++) {
#pragma unroll
            for (int r = 0; r < RANK; r++) red[warp][n * 9 + r] = acc[n][r];
            red[warp][n * 9 + 8] = sq[n];
        }
    }
    __syncthreads();

    if (tid < 36) {
        float s = 0.f;
#pragma unroll
        for (int w = 0; w < 8; w++) s += red[w][tid];
        const int n = tid / 9, k = tid % 9;
        if (is_bw) {
            if (k < 8) g_wA[(grow0 + n) * RANK + k] = s;
            else       g_w2[grow0 + n] = s;
        } else {
            if (k < 8) g_lxr[(grow0 - D_OUT + n) * RANK + k] = s;
        }
    }
}
__device__ const float* g_Aptr;

// tiny setter so rowdot can see A without an extra param reload per block
__global__ void set_aptr_kernel(const float* A) { g_Aptr = A; }

// ---------------------------------------------------------------------------
// scale: mag_scale[o] = mag[o] / (sqrt(w2 + 2s B.wA + s^2 B^T G B) + eps)
//        Bs[o,r] = B[o,r] * SCALING * mag_scale[o]
// ---------------------------------------------------------------------------
__global__ __launch_bounds__(256)
void scale_kernel(const float* __restrict__ Bm,
                  const float* __restrict__ mag)
{
    __shared__ float Gs[RANK * RANK];
    const int tid = threadIdx.x;
    if (tid < RANK * RANK) Gs[tid] = g_G[tid];
    __syncthreads();

    const int o = blockIdx.x * 256 + tid;

    float B[RANK], wA[RANK];
#pragma unroll
    for (int r = 0; r < RANK; r++) {
        B[r]  = __ldg(&Bm[o * RANK + r]);
        wA[r] = g_wA[o * RANK + r];
    }

    float lin = 0.f, quad = 0.f;
#pragma unroll
    for (int r = 0; r < RANK; r++) {
        lin += B[r] * wA[r];
        float t = 0.f;
#pragma unroll
        for (int r2 = 0; r2 < RANK; r2++)
            t += B[r2] * Gs[r * RANK + r2];
        quad += B[r] * t;
    }

    float n2 = g_w2[o] + 2.f * SCALING * lin + SCALING * SCALING * quad;
    float ms = __ldg(&mag[o]) / (sqrtf(n2) + EPS);
    g_mag_scale[o] = ms;
    float sc = SCALING * ms;
#pragma unroll
    for (int r = 0; r < RANK; r++)
        g_Bs[o * RANK + r] = B[r] * sc;
}

// ---------------------------------------------------------------------------
// out: out[s,o] = base_output[s,o]*mag_scale[o] + dot(lxr[s,:], Bs[o,:])
// 64 rows x 1024 cols per block; per-thread column Bs/ms in registers,
// streaming loads/stores.
// ---------------------------------------------------------------------------
__global__ __launch_bounds__(256)
void out_kernel(const float* __restrict__ bo, float* __restrict__ out)
{
    __shared__ float lxs[64 * RANK];            // 512 floats
    const int tid  = threadIdx.x;
    const int row0 = blockIdx.y * 64;
    const int c4g  = blockIdx.x * 256 + tid;    // global float4 column

    lxs[tid]       = g_lxr[row0 * RANK + tid];
    lxs[tid + 256] = g_lxr[row0 * RANK + 256 + tid];
    __syncthreads();

    const float4 ms4 = __ldg(&((const float4*)g_mag_scale)[c4g]);

    float Bsf[32];                              // Bsf[k*8 + r] = Bs[col k][r]
#pragma unroll
    for (int k = 0; k < 4; k++) {
        const int col = c4g * 4 + k;
        float4 v0 = __ldg(&((const float4*)g_Bs)[col * 2 + 0]);
        float4 v1 = __ldg(&((const float4*)g_Bs)[col * 2 + 1]);
        Bsf[k * 8 + 0] = v0.x; Bsf[k * 8 + 1] = v0.y;
        Bsf[k * 8 + 2] = v0.z; Bsf[k * 8 + 3] = v0.w;
        Bsf[k * 8 + 4] = v1.x; Bsf[k * 8 + 5] = v1.y;
        Bsf[k * 8 + 6] = v1.z; Bsf[k * 8 + 7] = v1.w;
    }

#pragma unroll 8
    for (int rl = 0; rl < 64; rl++) {
        const int row = row0 + rl;
        float4 b = __ldcs(&((const float4*)(bo + (size_t)row * D_OUT))[c4g]);

        float4 l0 = *((const float4*)&lxs[rl * RANK]);
        float4 l1 = *((const float4*)&lxs[rl * RANK + 4]);
        float lx[8] = { l0.x, l0.y, l0.z, l0.w, l1.x, l1.y, l1.z, l1.w };

        float o0 = b.x * ms4.x;
        float o1 = b.y * ms4.y;
        float o2 = b.z * ms4.z;
        float o3 = b.w * ms4.w;
#pragma unroll
        for (int r = 0; r < RANK; r++) {
            o0 += lx[r] * Bsf[0 * 8 + r];
            o1 += lx[r] * Bsf[1 * 8 + r];
            o2 += lx[r] * Bsf[2 * 8 + r];
            o3 += lx[r] * Bsf[3 * 8 + r];
        }
        __stcs(&((float4*)(out + (size_t)row * D_OUT))[c4g],
               make_float4(o0, o1, o2, o3));
    }
}

// ---------------------------------------------------------------------------
extern "C" void kernel_launch(void* const* d_in, const int* in_sizes, int n_in,
                              void* d_out, int out_size)
{
    const float* x   = (const float*)d_in[0];   // [8192, 4096]
    const float* bo  = (const float*)d_in[1];   // [8192, 4096]
    const float* bw  = (const float*)d_in[2];   // [4096, 4096]
    const float* A   = (const float*)d_in[3];   // [8, 4096]
    const float* Bm  = (const float*)d_in[4];   // [4096, 8]
    const float* mag = (const float*)d_in[5];   // [4096]
    float* out = (float*)d_out;                 // [8192, 4096]

    set_aptr_kernel<<<1, 1>>>(A);
    gram_kernel<<<1, 256>>>(A);
    rowdot_kernel<<<(D_OUT + NROWS) / 4, 256>>>(bw, x);
    scale_kernel<<<D_OUT / 256, 256>>>(Bm, mag);
    dim3 g3(D_OUT / 1024, NROWS / 64);
    out_kernel<<<g3, 256>>>(bo, out);
}